// round 13
// baseline (speedup 1.0000x reference)
#include <cuda_runtime.h>
#include <cuda_bf16.h>
#include <cuda_fp16.h>
#include <math.h>
#include <stdint.h>

#define DD    4096
#define NT    512
#define NV4   2          // float4 groups per thread PER ROW (512*2*4 = 4096)
#define K16   16
#define CAPT  224
#define CAPB  192
#define NW    (NT / 32)  // 16 warps

#define TH_TOP 2.7f
#define TH_BOT 0.02f

__device__ float    g_rstd[DD];
__device__ float    g_nmr[DD];
__device__ uint4    g_rn4[DD / 4];  // bf16 pairs {r01,n01,r23,n23}
__device__ uint2    g_e2[DD / 4];   // bf16 pairs of ema_out {e01,e23}
__device__ float    g_scal[8];      // 0:tau 1:beta_up 2:gamma 3:beta_fam 4:inv_norm_e

__device__ __forceinline__ float tanha(float a) {
    float r; asm("tanh.approx.f32 %0, %1;" : "=f"(r) : "f"(a)); return r;
}
__device__ __forceinline__ __nv_bfloat162 u2b(unsigned u) {
    return *reinterpret_cast<__nv_bfloat162*>(&u);
}
__device__ __forceinline__ unsigned b2u(__nv_bfloat162 h) {
    return *reinterpret_cast<unsigned*>(&h);
}

__global__ void prep_kernel(const float* __restrict__ ema_mean,
                            const float* __restrict__ ema_sq,
                            const float* __restrict__ ema_out,
                            const float* __restrict__ p_lt,
                            const float* __restrict__ p_lbu,
                            const float* __restrict__ p_lg,
                            const float* __restrict__ p_lbf) {
    __shared__ float sp[8];
    int tid = threadIdx.x;
    float acc = 0.0f;
    for (int i4 = tid; i4 < DD / 4; i4 += 256) {
        float r[4], n[4], e[4];
        #pragma unroll
        for (int c = 0; c < 4; c++) {
            int i = i4 * 4 + c;
            float m = ema_mean[i];
            float v = fmaxf(ema_sq[i] - m * m, 1e-4f);
            float rr = 1.0f / (sqrtf(v) + 1e-5f);
            float nn = -m * rr;
            g_rstd[i] = rr;
            g_nmr[i]  = nn;
            r[c] = rr; n[c] = nn;
            e[c] = ema_out[i];
            acc = fmaf(e[c], e[c], acc);
        }
        uint4 u;
        u.x = b2u(__floats2bfloat162_rn(r[0], r[1]));
        u.y = b2u(__floats2bfloat162_rn(n[0], n[1]));
        u.z = b2u(__floats2bfloat162_rn(r[2], r[3]));
        u.w = b2u(__floats2bfloat162_rn(n[2], n[3]));
        g_rn4[i4] = u;
        uint2 w;
        w.x = b2u(__floats2bfloat162_rn(e[0], e[1]));
        w.y = b2u(__floats2bfloat162_rn(e[2], e[3]));
        g_e2[i4] = w;
    }
    #pragma unroll
    for (int o = 16; o; o >>= 1) acc += __shfl_xor_sync(0xffffffffu, acc, o);
    if ((tid & 31) == 0) sp[tid >> 5] = acc;
    __syncthreads();
    if (tid == 0) {
        float s = 0.0f;
        #pragma unroll
        for (int w = 0; w < 8; w++) s += sp[w];
        g_scal[0] = expf(p_lt[0]);
        g_scal[1] = log1pf(expf(p_lbu[0]));
        g_scal[2] = log1pf(expf(p_lg[0]));
        g_scal[3] = 1.0f / (1.0f + expf(-p_lbf[0]));
        g_scal[4] = 1.0f / fmaxf(sqrtf(s), 1e-12f);
    }
}

#define INS8_TOP(v) do { float _l=(v), _u;                          \
    _u=fmaxf(r0,_l); _l=fminf(r0,_l); r0=_u;                        \
    _u=fmaxf(r1,_l); _l=fminf(r1,_l); r1=_u;                        \
    _u=fmaxf(r2,_l); _l=fminf(r2,_l); r2=_u;                        \
    _u=fmaxf(r3,_l); _l=fminf(r3,_l); r3=_u;                        \
    _u=fmaxf(r4,_l); _l=fminf(r4,_l); r4=_u;                        \
    _u=fmaxf(r5,_l); _l=fminf(r5,_l); r5=_u;                        \
    _u=fmaxf(r6,_l); _l=fminf(r6,_l); r6=_u;                        \
    r7=fmaxf(r7,_l); } while(0)

#define INS8_BOT(v) do { float _l=(v), _u;                          \
    _u=fminf(r0,_l); _l=fmaxf(r0,_l); r0=_u;                        \
    _u=fminf(r1,_l); _l=fmaxf(r1,_l); r1=_u;                        \
    _u=fminf(r2,_l); _l=fmaxf(r2,_l); r2=_u;                        \
    _u=fminf(r3,_l); _l=fmaxf(r3,_l); r3=_u;                        \
    _u=fminf(r4,_l); _l=fmaxf(r4,_l); r4=_u;                        \
    _u=fminf(r5,_l); _l=fmaxf(r5,_l); r5=_u;                        \
    _u=fminf(r6,_l); _l=fmaxf(r6,_l); r6=_u;                        \
    r7=fminf(r7,_l); } while(0)

__global__ __launch_bounds__(NT, 3)
void gelu_gate_kernel(const float* __restrict__ x,
                      float* __restrict__ out,
                      int nrows) {
    __shared__ float s_tz[2 * CAPT];
    __shared__ int   s_ti[2 * CAPT];
    __shared__ float s_bz[2 * CAPB];
    __shared__ int   s_bi[2 * CAPB];
    __shared__ int   s_cnt[4];          // topA, botA, topB, botB
    __shared__ float s_part[4 * NW];    // s2A, sdA, s2B, sdB per warp
    __shared__ float s_res[8];          // v16A w16A v16B w16B gcA gcB
    __shared__ int   s_flag;

    const int tid = threadIdx.x;
    const int rowA = blockIdx.x * 2;
    const int rowB = (rowA + 1 < nrows) ? rowA + 1 : rowA;
    const float* xrowA = x + (size_t)rowA * DD;
    const float* xrowB = x + (size_t)rowB * DD;
    const float4* xrA = reinterpret_cast<const float4*>(xrowA);
    const float4* xrB = reinterpret_cast<const float4*>(xrowB);
    float* orowA = out + (size_t)rowA * DD;
    float* orowB = out + (size_t)rowB * DD;

    const float G0 = 0.7978845608028654f;
    const float G1 = 0.044715f * 0.7978845608028654f;
    const float INF = __int_as_float(0x7f800000);
    const __nv_bfloat162 TT2 = __float2bfloat162_rn(TH_TOP);
    const __nv_bfloat162 TB2 = __float2bfloat162_rn(TH_BOT);

    if (tid < 4) s_cnt[tid] = 0;
    if (tid == 0) s_flag = 0;
    __syncthreads();

    __half2 ghA[2 * NV4], ghB[2 * NV4];
    float s2A = 0.f, sdA = 0.f, s2B = 0.f, sdB = 0.f;
    unsigned maskA = 0u, maskB = 0u;    // 4 bits each (2 iters x 2 pairs)

    #pragma unroll
    for (int i = 0; i < NV4; i++) {
        int idx4 = i * NT + tid;
        float4 xvA = xrA[idx4];
        float4 xvB = xrB[idx4];
        uint4  rv  = g_rn4[idx4];
        uint2  ev  = g_e2[idx4];
        float e0 = __bfloat162float(__low2bfloat16(u2b(ev.x)));
        float e1 = __bfloat162float(__high2bfloat16(u2b(ev.x)));
        float e2 = __bfloat162float(__low2bfloat16(u2b(ev.y)));
        float e3 = __bfloat162float(__high2bfloat16(u2b(ev.y)));
        // row A
        {
            float gg[4];
            #pragma unroll
            for (int c = 0; c < 4; c++) {
                float xx = (c==0)?xvA.x:(c==1)?xvA.y:(c==2)?xvA.z:xvA.w;
                float x2 = xx * xx;
                float u  = xx * fmaf(x2, G1, G0);
                float t  = tanha(u);
                float hx = 0.5f * xx;
                float g  = fmaf(hx, t, hx);
                s2A = fmaf(g, g, s2A);
                gg[c] = g;
            }
            sdA = fmaf(gg[0], e0, sdA); sdA = fmaf(gg[1], e1, sdA);
            sdA = fmaf(gg[2], e2, sdA); sdA = fmaf(gg[3], e3, sdA);
            ghA[i*2+0] = __floats2half2_rn(gg[0], gg[1]);
            ghA[i*2+1] = __floats2half2_rn(gg[2], gg[3]);
            __nv_bfloat162 xp0 = __floats2bfloat162_rn(xvA.x, xvA.y);
            __nv_bfloat162 xp1 = __floats2bfloat162_rn(xvA.z, xvA.w);
            __nv_bfloat162 a0 = __habs2(__hfma2(xp0, u2b(rv.x), u2b(rv.y)));
            __nv_bfloat162 a1 = __habs2(__hfma2(xp1, u2b(rv.z), u2b(rv.w)));
            unsigned h0 = b2u(__hgt2(a0, TT2)) | b2u(__hlt2(a0, TB2));
            unsigned h1 = b2u(__hgt2(a1, TT2)) | b2u(__hlt2(a1, TB2));
            maskA |= h0 ? (1u << (i*2+0)) : 0u;
            maskA |= h1 ? (1u << (i*2+1)) : 0u;
        }
        // row B
        {
            float gg[4];
            #pragma unroll
            for (int c = 0; c < 4; c++) {
                float xx = (c==0)?xvB.x:(c==1)?xvB.y:(c==2)?xvB.z:xvB.w;
                float x2 = xx * xx;
                float u  = xx * fmaf(x2, G1, G0);
                float t  = tanha(u);
                float hx = 0.5f * xx;
                float g  = fmaf(hx, t, hx);
                s2B = fmaf(g, g, s2B);
                gg[c] = g;
            }
            sdB = fmaf(gg[0], e0, sdB); sdB = fmaf(gg[1], e1, sdB);
            sdB = fmaf(gg[2], e2, sdB); sdB = fmaf(gg[3], e3, sdB);
            ghB[i*2+0] = __floats2half2_rn(gg[0], gg[1]);
            ghB[i*2+1] = __floats2half2_rn(gg[2], gg[3]);
            __nv_bfloat162 xp0 = __floats2bfloat162_rn(xvB.x, xvB.y);
            __nv_bfloat162 xp1 = __floats2bfloat162_rn(xvB.z, xvB.w);
            __nv_bfloat162 a0 = __habs2(__hfma2(xp0, u2b(rv.x), u2b(rv.y)));
            __nv_bfloat162 a1 = __habs2(__hfma2(xp1, u2b(rv.z), u2b(rv.w)));
            unsigned h0 = b2u(__hgt2(a0, TT2)) | b2u(__hlt2(a0, TB2));
            unsigned h1 = b2u(__hgt2(a1, TT2)) | b2u(__hlt2(a1, TB2));
            maskB |= h0 ? (1u << (i*2+0)) : 0u;
            maskB |= h1 ? (1u << (i*2+1)) : 0u;
        }
    }

    #pragma unroll
    for (int o = 16; o; o >>= 1) {
        s2A += __shfl_xor_sync(0xffffffffu, s2A, o);
        sdA += __shfl_xor_sync(0xffffffffu, sdA, o);
        s2B += __shfl_xor_sync(0xffffffffu, s2B, o);
        sdB += __shfl_xor_sync(0xffffffffu, sdB, o);
    }
    if ((tid & 31) == 0) {
        int w = tid >> 5;
        s_part[0*NW + w] = s2A;
        s_part[1*NW + w] = sdA;
        s_part[2*NW + w] = s2B;
        s_part[3*NW + w] = sdB;
    }

    // ---- deferred pushes (exact fp32 z) ----
    unsigned m = maskA;
    while (m) {
        int pr = __ffs(m) - 1; m &= m - 1;
        int base = (((pr >> 1) * NT + tid) << 2) + (pr & 1) * 2;
        #pragma unroll
        for (int h = 0; h < 2; h++) {
            int idx = base + h;
            float xx = __ldg(xrowA + idx);
            float zz = fmaf(xx, __ldg(g_rstd + idx), __ldg(g_nmr + idx));
            float az = fabsf(zz);
            if (az > TH_TOP) {
                int q = atomicAdd(&s_cnt[0], 1);
                if (q < CAPT) { s_tz[q] = zz; s_ti[q] = idx; }
            } else if (az < TH_BOT) {
                int q = atomicAdd(&s_cnt[1], 1);
                if (q < CAPB) { s_bz[q] = az; s_bi[q] = idx; }
            }
        }
    }
    m = maskB;
    while (m) {
        int pr = __ffs(m) - 1; m &= m - 1;
        int base = (((pr >> 1) * NT + tid) << 2) + (pr & 1) * 2;
        #pragma unroll
        for (int h = 0; h < 2; h++) {
            int idx = base + h;
            float xx = __ldg(xrowB + idx);
            float zz = fmaf(xx, __ldg(g_rstd + idx), __ldg(g_nmr + idx));
            float az = fabsf(zz);
            if (az > TH_TOP) {
                int q = atomicAdd(&s_cnt[2], 1);
                if (q < CAPT) { s_tz[CAPT + q] = zz; s_ti[CAPT + q] = idx; }
            } else if (az < TH_BOT) {
                int q = atomicAdd(&s_cnt[3], 1);
                if (q < CAPB) { s_bz[CAPB + q] = az; s_bi[CAPB + q] = idx; }
            }
        }
    }
    __syncthreads();   // barrier A

    // ---- rare retry loop (block-uniform; never fires in practice) ----
    {
        float thTA = TH_TOP, thBA = TH_BOT, thTB = TH_TOP, thBB = TH_BOT;
        for (int tries = 0; tries < 12; ++tries) {
            int cta = s_cnt[0], cba = s_cnt[1], ctb = s_cnt[2], cbb = s_cnt[3];
            bool bTA = (cta < K16) | (cta > CAPT);
            bool bBA = (cba < K16) | (cba > CAPB);
            bool bTB = (ctb < K16) | (ctb > CAPT);
            bool bBB = (cbb < K16) | (cbb > CAPB);
            if (!(bTA | bBA | bTB | bBB)) break;
            if (bTA) thTA = (cta < K16) ? thTA * 0.5f : thTA * 1.4f;
            if (bBA) thBA = (cba < K16) ? thBA * 2.0f : thBA * 0.5f;
            if (bTB) thTB = (ctb < K16) ? thTB * 0.5f : thTB * 1.4f;
            if (bBB) thBB = (cbb < K16) ? thBB * 2.0f : thBB * 0.5f;
            __syncthreads();
            if (tid == 0) {
                s_flag = 1;
                if (bTA) s_cnt[0] = 0; if (bBA) s_cnt[1] = 0;
                if (bTB) s_cnt[2] = 0; if (bBB) s_cnt[3] = 0;
            }
            __syncthreads();
            for (int i = 0; i < NV4; i++) {
                int idx4 = i * NT + tid;
                float4 xvA = xrA[idx4];
                float4 xvB = xrB[idx4];
                #pragma unroll
                for (int c = 0; c < 4; c++) {
                    int idx = idx4 * 4 + c;
                    float rr = __ldg(g_rstd + idx);
                    float nn = __ldg(g_nmr + idx);
                    float xa = (c==0)?xvA.x:(c==1)?xvA.y:(c==2)?xvA.z:xvA.w;
                    float xb = (c==0)?xvB.x:(c==1)?xvB.y:(c==2)?xvB.z:xvB.w;
                    float zar = fmaf(xa, rr, nn);
                    float zbr = fmaf(xb, rr, nn);
                    float za = fabsf(zar);
                    float zb = fabsf(zbr);
                    if (bTA && za > thTA) {
                        int q = atomicAdd(&s_cnt[0], 1);
                        if (q < CAPT) { s_tz[q] = zar; s_ti[q] = idx; }
                    }
                    if (bBA && za < thBA) {
                        int q = atomicAdd(&s_cnt[1], 1);
                        if (q < CAPB) { s_bz[q] = za; s_bi[q] = idx; }
                    }
                    if (bTB && zb > thTB) {
                        int q = atomicAdd(&s_cnt[2], 1);
                        if (q < CAPT) { s_tz[CAPT + q] = zbr; s_ti[CAPT + q] = idx; }
                    }
                    if (bBB && zb < thBB) {
                        int q = atomicAdd(&s_cnt[3], 1);
                        if (q < CAPB) { s_bz[CAPB + q] = zb; s_bi[CAPB + q] = idx; }
                    }
                }
            }
            __syncthreads();
        }
    }

    // ---- parallel selection + cosine: warps 0-5 ----
    const int wid = tid >> 5, lane = tid & 31;
    if (wid == 0 || wid == 2) {
        int r = (wid == 0) ? 0 : 1;
        int ct = min(s_cnt[r * 2], CAPT);
        const float* tz = s_tz + r * CAPT;
        float r0=-1.f,r1=-1.f,r2=-1.f,r3=-1.f,r4=-1.f,r5=-1.f,r6=-1.f,r7=-1.f;
        for (int k = lane; k < ct; k += 32) {
            float v = fabsf(tz[k]);
            INS8_TOP(v);
        }
        float last = -1.f;
        #pragma unroll
        for (int it = 0; it < K16; it++) {
            float mm = r0;
            #pragma unroll
            for (int o = 16; o; o >>= 1) mm = fmaxf(mm, __shfl_xor_sync(0xffffffffu, mm, o));
            last = mm;
            if (r0 == mm) { r0=r1; r1=r2; r2=r3; r3=r4; r4=r5; r5=r6; r6=r7; r7=-1.f; }
        }
        if (lane == 0) s_res[r * 2 + 0] = last;
    } else if (wid == 1 || wid == 3) {
        int r = (wid == 1) ? 0 : 1;
        int cb = min(s_cnt[r * 2 + 1], CAPB);
        const float* bz = s_bz + r * CAPB;
        float r0=INF,r1=INF,r2=INF,r3=INF,r4=INF,r5=INF,r6=INF,r7=INF;
        for (int k = lane; k < cb; k += 32) {
            float v = bz[k];
            INS8_BOT(v);
        }
        float last = INF;
        #pragma unroll
        for (int it = 0; it < K16; it++) {
            float mm = r0;
            #pragma unroll
            for (int o = 16; o; o >>= 1) mm = fminf(mm, __shfl_xor_sync(0xffffffffu, mm, o));
            last = mm;
            if (r0 == mm) { r0=r1; r1=r2; r2=r3; r3=r4; r4=r5; r5=r6; r6=r7; r7=INF; }
        }
        if (lane == 0) s_res[r * 2 + 1] = last;
    } else if (wid == 4 || wid == 5) {
        int r = (wid == 4) ? 0 : 1;
        float a = 0.f, b = 0.f;
        if (lane < NW) { a = s_part[(r*2+0)*NW + lane]; b = s_part[(r*2+1)*NW + lane]; }
        #pragma unroll
        for (int o = 8; o; o >>= 1) {
            a += __shfl_xor_sync(0xffffffffu, a, o);
            b += __shfl_xor_sync(0xffffffffu, b, o);
        }
        if (lane == 0) {
            float inv = rsqrtf(fmaxf(a, 1e-24f));
            float cs  = fminf(fmaxf(b * g_scal[4] * inv, -1.0f), 1.0f);
            s_res[4 + r] = __expf(-g_scal[0] * cs);
        }
    }
    __syncthreads();   // barrier B: thresholds + gc visible

    const float bu = g_scal[1];
    const float gm = g_scal[2];
    const float bf = g_scal[3];
    const int flag = s_flag;

    // ---- epilogue: single-pass gated store (normal) or plain store (retry) ----
    #pragma unroll
    for (int r = 0; r < 2; r++) {
        const float v16 = s_res[r * 2 + 0];
        const float w16 = s_res[r * 2 + 1];
        const float gc  = s_res[4 + r];
        const unsigned mk = (r == 0) ? maskA : maskB;
        const float* xrw = (r == 0) ? xrowA : xrowB;
        float* orw = (r == 0) ? orowA : orowB;
        float4* orw4 = reinterpret_cast<float4*>(orw);
        const __half2* gh = (r == 0) ? ghA : ghB;
        #pragma unroll
        for (int i = 0; i < NV4; i++) {
            float2 f0 = __half22float2(gh[i*2+0]);
            float2 f1 = __half22float2(gh[i*2+1]);
            float ga[4] = {1.f, 1.f, 1.f, 1.f};
            unsigned mb = (mk >> (i * 2)) & 3u;
            if (mb && !flag) {
                #pragma unroll
                for (int p = 0; p < 2; p++) {
                    if ((mb >> p) & 1u) {
                        #pragma unroll
                        for (int h = 0; h < 2; h++) {
                            int idx = ((i * NT + tid) << 2) + p * 2 + h;
                            float xx = __ldg(xrw + idx);
                            float zz = fmaf(xx, __ldg(g_rstd + idx), __ldg(g_nmr + idx));
                            float az = fabsf(zz);
                            float gv = 1.0f;
                            if (az >= v16)
                                gv = fminf(fmaxf(fmaf(bu, tanhf(gm * zz), 1.0f), 0.1f), 8.0f);
                            if (az <= w16) gv = bf;
                            ga[p*2+h] = gv;
                        }
                    }
                }
            }
            float4 ov;
            ov.x = f0.x * ga[0] * gc;
            ov.y = f0.y * ga[1] * gc;
            ov.z = f1.x * ga[2] * gc;
            ov.w = f1.y * ga[3] * gc;
            orw4[i * NT + tid] = ov;
        }
    }

    // ---- fallback patch path (only if retry fired; block-uniform) ----
    if (flag) {
        __syncthreads();
        if (wid == 0 || wid == 2) {
            int r = (wid == 0) ? 0 : 1;
            const float v16 = s_res[r * 2 + 0];
            float* orw = (r == 0) ? orowA : orowB;
            int ct = min(s_cnt[r * 2], CAPT);
            const float* tz = s_tz + r * CAPT;
            const int*   ti = s_ti + r * CAPT;
            for (int k = lane; k < ct; k += 32) {
                float zz = tz[k];
                if (fabsf(zz) >= v16) {
                    float gate = fminf(fmaxf(fmaf(bu, tanhf(gm * zz), 1.0f), 0.1f), 8.0f);
                    orw[ti[k]] = orw[ti[k]] * gate;
                }
            }
        } else if (wid == 1 || wid == 3) {
            int r = (wid == 1) ? 0 : 1;
            const float w16 = s_res[r * 2 + 1];
            float* orw = (r == 0) ? orowA : orowB;
            int cb = min(s_cnt[r * 2 + 1], CAPB);
            const float* bz = s_bz + r * CAPB;
            const int*   bi = s_bi + r * CAPB;
            for (int k = lane; k < cb; k += 32) {
                if (bz[k] <= w16) {
                    orw[bi[k]] = orw[bi[k]] * bf;
                }
            }
        }
    }
}

extern "C" void kernel_launch(void* const* d_in, const int* in_sizes, int n_in,
                              void* d_out, int out_size) {
    const float* x        = (const float*)d_in[0];
    const float* ema_mean = (const float*)d_in[1];
    const float* ema_sq   = (const float*)d_in[2];
    const float* ema_out  = (const float*)d_in[3];
    const float* lt       = (const float*)d_in[4];
    const float* lbu      = (const float*)d_in[5];
    const float* lg       = (const float*)d_in[6];
    const float* lbf      = (const float*)d_in[7];
    float* out = (float*)d_out;

    int rows = in_sizes[0] / DD;
    if (rows < 1) rows = 1;
    int blocks = (rows + 1) / 2;

    prep_kernel<<<1, 256>>>(ema_mean, ema_sq, ema_out, lt, lbu, lg, lbf);
    gelu_gate_kernel<<<blocks, NT>>>(x, out, rows);
}

// round 14
// speedup vs baseline: 1.4601x; 1.4601x over previous
#include <cuda_runtime.h>
#include <cuda_bf16.h>
#include <cuda_fp16.h>
#include <math.h>
#include <stdint.h>

#define DD    4096
#define NT    256
#define NV4   4          // float4 groups per thread
#define K16   16
#define CAPT  224
#define CAPB  192

#define TH_TOP 2.7f
#define TH_BOT 0.02f

__device__ float    g_rstd[DD];     // exact 1/(std+eps)
__device__ float    g_nmr[DD];      // exact -mean*rstd
__device__ uint4    g_rn4[DD / 4];  // bf16 pairs {r01,n01,r23,n23} (filter only)
__device__ uint2    g_e2[DD / 4];   // bf16 pairs of ema_out {e01,e23}
__device__ float    g_scal[8];      // 0:tau 1:beta_up 2:gamma 3:beta_fam 4:inv_norm_e

__device__ __forceinline__ float tanha(float a) {
    float r; asm("tanh.approx.f32 %0, %1;" : "=f"(r) : "f"(a)); return r;
}
__device__ __forceinline__ __nv_bfloat162 u2b(unsigned u) {
    return *reinterpret_cast<__nv_bfloat162*>(&u);
}
__device__ __forceinline__ unsigned b2u(__nv_bfloat162 h) {
    return *reinterpret_cast<unsigned*>(&h);
}
__device__ __forceinline__ uint32_t smem_u32(const void* p) {
    uint32_t a;
    asm("{ .reg .u64 t; cvta.to.shared.u64 t, %1; cvt.u32.u64 %0, t; }" : "=r"(a) : "l"(p));
    return a;
}

__global__ void prep_kernel(const float* __restrict__ ema_mean,
                            const float* __restrict__ ema_sq,
                            const float* __restrict__ ema_out,
                            const float* __restrict__ p_lt,
                            const float* __restrict__ p_lbu,
                            const float* __restrict__ p_lg,
                            const float* __restrict__ p_lbf) {
    __shared__ float sp[8];
    int tid = threadIdx.x;
    float acc = 0.0f;
    for (int i4 = tid; i4 < DD / 4; i4 += 256) {
        float r[4], n[4], e[4];
        #pragma unroll
        for (int c = 0; c < 4; c++) {
            int i = i4 * 4 + c;
            float m = ema_mean[i];
            float v = fmaxf(ema_sq[i] - m * m, 1e-4f);
            float rr = 1.0f / (sqrtf(v) + 1e-5f);
            float nn = -m * rr;
            g_rstd[i] = rr;
            g_nmr[i]  = nn;
            r[c] = rr; n[c] = nn;
            e[c] = ema_out[i];
            acc = fmaf(e[c], e[c], acc);
        }
        uint4 u;
        u.x = b2u(__floats2bfloat162_rn(r[0], r[1]));
        u.y = b2u(__floats2bfloat162_rn(n[0], n[1]));
        u.z = b2u(__floats2bfloat162_rn(r[2], r[3]));
        u.w = b2u(__floats2bfloat162_rn(n[2], n[3]));
        g_rn4[i4] = u;
        uint2 w;
        w.x = b2u(__floats2bfloat162_rn(e[0], e[1]));
        w.y = b2u(__floats2bfloat162_rn(e[2], e[3]));
        g_e2[i4] = w;
    }
    #pragma unroll
    for (int o = 16; o; o >>= 1) acc += __shfl_xor_sync(0xffffffffu, acc, o);
    if ((tid & 31) == 0) sp[tid >> 5] = acc;
    __syncthreads();
    if (tid == 0) {
        float s = 0.0f;
        #pragma unroll
        for (int w = 0; w < 8; w++) s += sp[w];
        g_scal[0] = expf(p_lt[0]);
        g_scal[1] = log1pf(expf(p_lbu[0]));
        g_scal[2] = log1pf(expf(p_lg[0]));
        g_scal[3] = 1.0f / (1.0f + expf(-p_lbf[0]));
        g_scal[4] = 1.0f / fmaxf(sqrtf(s), 1e-12f);
    }
}

#define INS8_TOP(v) do { float _l=(v), _u;                          \
    _u=fmaxf(r0,_l); _l=fminf(r0,_l); r0=_u;                        \
    _u=fmaxf(r1,_l); _l=fminf(r1,_l); r1=_u;                        \
    _u=fmaxf(r2,_l); _l=fminf(r2,_l); r2=_u;                        \
    _u=fmaxf(r3,_l); _l=fminf(r3,_l); r3=_u;                        \
    _u=fmaxf(r4,_l); _l=fminf(r4,_l); r4=_u;                        \
    _u=fmaxf(r5,_l); _l=fminf(r5,_l); r5=_u;                        \
    _u=fmaxf(r6,_l); _l=fminf(r6,_l); r6=_u;                        \
    r7=fmaxf(r7,_l); } while(0)

#define INS8_BOT(v) do { float _l=(v), _u;                          \
    _u=fminf(r0,_l); _l=fmaxf(r0,_l); r0=_u;                        \
    _u=fminf(r1,_l); _l=fmaxf(r1,_l); r1=_u;                        \
    _u=fminf(r2,_l); _l=fmaxf(r2,_l); r2=_u;                        \
    _u=fminf(r3,_l); _l=fmaxf(r3,_l); r3=_u;                        \
    _u=fminf(r4,_l); _l=fmaxf(r4,_l); r4=_u;                        \
    _u=fminf(r5,_l); _l=fmaxf(r5,_l); r5=_u;                        \
    _u=fminf(r6,_l); _l=fmaxf(r6,_l); r6=_u;                        \
    r7=fminf(r7,_l); } while(0)

__global__ __launch_bounds__(NT, 8)
void gelu_gate_kernel(const float* __restrict__ x,
                      float* __restrict__ out) {
    __shared__ __align__(16) float s_x[DD];     // 16KB staged x row (TMA bulk)
    __shared__ __align__(8) unsigned long long s_mbar;
    __shared__ float s_tz[CAPT];
    __shared__ int   s_ti[CAPT];
    __shared__ float s_bz[CAPB];
    __shared__ int   s_bi[CAPB];
    __shared__ int   s_cnt[2];
    __shared__ float s_part[2 * (NT / 32)];

    const int tid = threadIdx.x;
    const float* xrow = x + (size_t)blockIdx.x * DD;
    float* orow = out + (size_t)blockIdx.x * DD;
    float4* orow4 = reinterpret_cast<float4*>(orow);
    const float4* xs4 = reinterpret_cast<const float4*>(s_x);
    const uint32_t mb = smem_u32(&s_mbar);
    const uint32_t xs = smem_u32(s_x);

    const float G0 = 0.7978845608028654f;
    const float G1 = 0.044715f * 0.7978845608028654f;
    const float INF = __int_as_float(0x7f800000);
    const __nv_bfloat162 TT2 = __float2bfloat162_rn(TH_TOP);
    const __nv_bfloat162 TB2 = __float2bfloat162_rn(TH_BOT);

    // ---- stage x row into smem via bulk async copy ----
    if (tid == 0) {
        s_cnt[0] = 0; s_cnt[1] = 0;
        asm volatile("mbarrier.init.shared.b64 [%0], %1;" :: "r"(mb), "r"(1) : "memory");
    }
    __syncthreads();
    if (tid == 0) {
        asm volatile("mbarrier.arrive.expect_tx.shared.b64 _, [%0], %1;"
                     :: "r"(mb), "r"((unsigned)(DD * 4)) : "memory");
        asm volatile("cp.async.bulk.shared::cta.global.mbarrier::complete_tx::bytes "
                     "[%0], [%1], %2, [%3];"
                     :: "r"(xs), "l"(xrow), "r"((unsigned)(DD * 4)), "r"(mb) : "memory");
    }
    // wait for x in smem
    {
        uint32_t done = 0;
        while (!done) {
            asm volatile(
                "{\n\t.reg .pred p;\n\t"
                "mbarrier.try_wait.parity.acquire.cta.shared::cta.b64 p, [%1], %2, 0x989680;\n\t"
                "selp.b32 %0, 1, 0, p;\n\t}"
                : "=r"(done) : "r"(mb), "r"(0u) : "memory");
        }
    }

    __half2 gh[2 * NV4];
    float s2 = 0.f, sd = 0.f;
    unsigned maskP = 0u;

    #pragma unroll
    for (int i = 0; i < NV4; i++) {
        int idx4 = i * NT + tid;
        float4 xv = xs4[idx4];
        uint4  rv = g_rn4[idx4];
        uint2  ev = g_e2[idx4];
        float gg[4];
        #pragma unroll
        for (int c = 0; c < 4; c++) {
            float xx = (c==0)?xv.x:(c==1)?xv.y:(c==2)?xv.z:xv.w;
            float x2 = xx * xx;
            float u  = xx * fmaf(x2, G1, G0);
            float t  = tanha(u);
            float hx = 0.5f * xx;
            float g  = fmaf(hx, t, hx);
            s2 = fmaf(g, g, s2);
            gg[c] = g;
        }
        {
            float e0 = __bfloat162float(__low2bfloat16(u2b(ev.x)));
            float e1 = __bfloat162float(__high2bfloat16(u2b(ev.x)));
            float e2 = __bfloat162float(__low2bfloat16(u2b(ev.y)));
            float e3 = __bfloat162float(__high2bfloat16(u2b(ev.y)));
            sd = fmaf(gg[0], e0, sd);
            sd = fmaf(gg[1], e1, sd);
            sd = fmaf(gg[2], e2, sd);
            sd = fmaf(gg[3], e3, sd);
        }
        gh[i*2+0] = __floats2half2_rn(gg[0], gg[1]);
        gh[i*2+1] = __floats2half2_rn(gg[2], gg[3]);
        {
            __nv_bfloat162 xp0 = __floats2bfloat162_rn(xv.x, xv.y);
            __nv_bfloat162 xp1 = __floats2bfloat162_rn(xv.z, xv.w);
            __nv_bfloat162 a0 = __habs2(__hfma2(xp0, u2b(rv.x), u2b(rv.y)));
            __nv_bfloat162 a1 = __habs2(__hfma2(xp1, u2b(rv.z), u2b(rv.w)));
            unsigned h0 = b2u(__hgt2(a0, TT2)) | b2u(__hlt2(a0, TB2));
            unsigned h1 = b2u(__hgt2(a1, TT2)) | b2u(__hlt2(a1, TB2));
            maskP |= h0 ? (1u << (i*2+0)) : 0u;
            maskP |= h1 ? (1u << (i*2+1)) : 0u;
        }
    }

    #pragma unroll
    for (int o = 16; o; o >>= 1) {
        s2 += __shfl_xor_sync(0xffffffffu, s2, o);
        sd += __shfl_xor_sync(0xffffffffu, sd, o);
    }
    if ((tid & 31) == 0) {
        s_part[(tid >> 5) * 2 + 0] = s2;
        s_part[(tid >> 5) * 2 + 1] = sd;
    }

    // ---- deferred pushes: exact fp32 z from smem x ----
    while (maskP) {
        int pr = __ffs(maskP) - 1;
        maskP &= maskP - 1;
        int i = pr >> 1, p = pr & 1;
        int base = (((i * NT) + tid) << 2) + p * 2;
        #pragma unroll
        for (int h = 0; h < 2; h++) {
            int idx = base + h;
            float xx = s_x[idx];
            float zz = fmaf(xx, __ldg(g_rstd + idx), __ldg(g_nmr + idx));
            float az = fabsf(zz);
            if (az > TH_TOP) {
                int q = atomicAdd(&s_cnt[0], 1);
                if (q < CAPT) { s_tz[q] = zz; s_ti[q] = idx; }
            } else if (az < TH_BOT) {
                int q = atomicAdd(&s_cnt[1], 1);
                if (q < CAPB) { s_bz[q] = az; s_bi[q] = idx; }
            }
        }
    }
    __syncthreads();   // barrier A

    // ---- rare retry loop (block-uniform; exact rescan from smem) ----
    {
        float thT = TH_TOP, thB = TH_BOT;
        for (int tries = 0; tries < 12; ++tries) {
            int ct = s_cnt[0], cb = s_cnt[1];
            bool badT = (ct < K16) | (ct > CAPT);
            bool badB = (cb < K16) | (cb > CAPB);
            if (!badT && !badB) break;
            if (badT) thT = (ct < K16) ? thT * 0.5f : thT * 1.4f;
            if (badB) thB = (cb < K16) ? thB * 2.0f : thB * 0.5f;
            __syncthreads();
            if (tid == 0) { if (badT) s_cnt[0] = 0; if (badB) s_cnt[1] = 0; }
            __syncthreads();
            for (int i = 0; i < NV4; i++) {
                int idx4 = i * NT + tid;
                float4 xv = xs4[idx4];
                #pragma unroll
                for (int c = 0; c < 4; c++) {
                    int idx = idx4 * 4 + c;
                    float xx = (c==0)?xv.x:(c==1)?xv.y:(c==2)?xv.z:xv.w;
                    float zz = fmaf(xx, __ldg(g_rstd + idx), __ldg(g_nmr + idx));
                    float az = fabsf(zz);
                    if (badT && az > thT) {
                        int q = atomicAdd(&s_cnt[0], 1);
                        if (q < CAPT) { s_tz[q] = zz; s_ti[q] = idx; }
                    }
                    if (badB && az < thB) {
                        int q = atomicAdd(&s_cnt[1], 1);
                        if (q < CAPB) { s_bz[q] = az; s_bi[q] = idx; }
                    }
                }
            }
            __syncthreads();
        }
    }

    // ---- cosine gate ----
    float a = 0.f, b = 0.f;
    #pragma unroll
    for (int w = 0; w < NT / 32; w++) { a += s_part[2*w]; b += s_part[2*w+1]; }
    float inv = rsqrtf(fmaxf(a, 1e-24f));
    float cs  = fminf(fmaxf(b * g_scal[4] * inv, -1.0f), 1.0f);
    const float gc = __expf(-g_scal[0] * cs);

    // ---- bulk store: out = half(g) * gc ----
    #pragma unroll
    for (int i = 0; i < NV4; i++) {
        float2 f0 = __half22float2(gh[i*2+0]);
        float2 f1 = __half22float2(gh[i*2+1]);
        float4 ov;
        ov.x = f0.x * gc;
        ov.y = f0.y * gc;
        ov.z = f1.x * gc;
        ov.w = f1.y * gc;
        orow4[i * NT + tid] = ov;
    }
    __syncthreads();   // barrier B

    // ---- selection + global patch (<=32 elements) ----
    const int wid = tid >> 5, lane = tid & 31;
    if (wid == 0) {
        int ct = min(s_cnt[0], CAPT);
        float r0=-1.f,r1=-1.f,r2=-1.f,r3=-1.f,r4=-1.f,r5=-1.f,r6=-1.f,r7=-1.f;
        for (int k = lane; k < ct; k += 32) {
            float v = fabsf(s_tz[k]);
            INS8_TOP(v);
        }
        float last = -1.f;
        #pragma unroll
        for (int it = 0; it < K16; it++) {
            float m = r0;
            #pragma unroll
            for (int o = 16; o; o >>= 1) m = fmaxf(m, __shfl_xor_sync(0xffffffffu, m, o));
            last = m;
            if (r0 == m) { r0=r1; r1=r2; r2=r3; r3=r4; r4=r5; r5=r6; r6=r7; r7=-1.f; }
        }
        const float v16 = last;
        const float bu = g_scal[1];
        const float gm = g_scal[2];
        for (int k = lane; k < ct; k += 32) {
            float zz = s_tz[k];
            if (fabsf(zz) >= v16) {
                int idx = s_ti[k];
                float gate = fminf(fmaxf(fmaf(bu, tanhf(gm * zz), 1.0f), 0.1f), 8.0f);
                orow[idx] = orow[idx] * gate;
            }
        }
    } else if (wid == 1) {
        int cb = min(s_cnt[1], CAPB);
        float r0=INF,r1=INF,r2=INF,r3=INF,r4=INF,r5=INF,r6=INF,r7=INF;
        for (int k = lane; k < cb; k += 32) {
            float v = s_bz[k];
            INS8_BOT(v);
        }
        float last = INF;
        #pragma unroll
        for (int it = 0; it < K16; it++) {
            float m = r0;
            #pragma unroll
            for (int o = 16; o; o >>= 1) m = fminf(m, __shfl_xor_sync(0xffffffffu, m, o));
            last = m;
            if (r0 == m) { r0=r1; r1=r2; r2=r3; r3=r4; r4=r5; r5=r6; r6=r7; r7=INF; }
        }
        const float w16 = last;
        const float bf = g_scal[3];
        for (int k = lane; k < cb; k += 32) {
            if (s_bz[k] <= w16) {
                int idx = s_bi[k];
                orow[idx] = orow[idx] * bf;
            }
        }
    }
}

extern "C" void kernel_launch(void* const* d_in, const int* in_sizes, int n_in,
                              void* d_out, int out_size) {
    const float* x        = (const float*)d_in[0];
    const float* ema_mean = (const float*)d_in[1];
    const float* ema_sq   = (const float*)d_in[2];
    const float* ema_out  = (const float*)d_in[3];
    const float* lt       = (const float*)d_in[4];
    const float* lbu      = (const float*)d_in[5];
    const float* lg       = (const float*)d_in[6];
    const float* lbf      = (const float*)d_in[7];
    float* out = (float*)d_out;

    int rows = in_sizes[0] / DD;
    if (rows < 1) rows = 1;

    prep_kernel<<<1, 256>>>(ema_mean, ema_sq, ema_out, lt, lbu, lg, lbf);
    gelu_gate_kernel<<<rows, NT>>>(x, out);
}